// round 15
// baseline (speedup 1.0000x reference)
#include <cuda_runtime.h>
#include <math.h>

#define BATCH 64
#define HID   1024
#define INP   1024
#define SPLITK 8
#define HB    (BATCH/2)          // half batch = 32

// ---------------- scratch (static device globals; no allocation) -------------
__device__ float g_part[SPLITK][6][BATCH][HID];  // split-K GEMM partials
__device__ float g_f [BATCH][HID];               // sigmoid(f_tilda)
__device__ float g_a [BATCH][HID];               // i_prime * v
__device__ float g_o [BATCH][HID];               // sigmoid(o_tilda)
__device__ float g_k [BATCH][HID];               // k_t (scaled by 1/32)
__device__ float g_q [BATCH][HID];               // q_t
__device__ float g_nq[BATCH];                    // sum_j n_t * q_t

struct WPtrs {
    const float* W[6];
    const float* b[6];
};

struct GemmSmem {                // 43008 bytes
    float xs[2][32][36];         // [buf][kk][m 0..31], pad to 36
    float ws[2][32][132];        // [buf][kk][n 0..127], pad to 132
};
struct UpdSmem {                 // 8192 bytes
    float sk[HID];
    float sq[HID];
};

// ---------------- GEMM half-batch device body --------------------------------
// BM=32 (half batch), BN=128, BK=32, 256 threads, 4x4 microtile.
// 2-stage smem ping-pong + register double-buffer; one barrier per kt.
// a-operand is a pure warp broadcast (ty constant within warp).
__device__ __forceinline__ void gemm_half(
    const float* __restrict__ x, const WPtrs& wp, int b0,
    int ntile, int g, int z, char* smem_raw)
{
    GemmSmem& S = *(GemmSmem*)smem_raw;
    const float* __restrict__ W = wp.W[g];

    const int tid = threadIdx.x;
    const int ty  = tid >> 5;        // 0..7  (m group of 4) — constant per warp
    const int tx  = tid & 31;        // 0..31 (n group of 4)
    const int n0  = ntile * 128;
    const int lm  = tid >> 3;        // 0..31 load row
    const int lk  = (tid & 7) * 4;   // 0,4,...,28

    float4 xr; float4 wr[4];

#define LDG_TILE(k0)                                                           \
    {                                                                          \
        xr = *(const float4*)(x + (size_t)(b0 + lm) * INP + (k0) + lk);        \
        _Pragma("unroll")                                                      \
        for (int i = 0; i < 4; ++i)                                            \
            wr[i] = *(const float4*)(W + (size_t)(n0 + lm + i * 32) * INP + (k0) + lk); \
    }

#define STS_TILE(buf)                                                          \
    {                                                                          \
        S.xs[buf][lk + 0][lm] = xr.x; S.xs[buf][lk + 1][lm] = xr.y;            \
        S.xs[buf][lk + 2][lm] = xr.z; S.xs[buf][lk + 3][lm] = xr.w;            \
        _Pragma("unroll")                                                      \
        for (int i = 0; i < 4; ++i) {                                          \
            int n = lm + i * 32;                                               \
            S.ws[buf][lk + 0][n] = wr[i].x; S.ws[buf][lk + 1][n] = wr[i].y;    \
            S.ws[buf][lk + 2][n] = wr[i].z; S.ws[buf][lk + 3][n] = wr[i].w;    \
        }                                                                      \
    }

    const int kbase = z * 128;

    LDG_TILE(kbase);
    STS_TILE(0);
    __syncthreads();

    float acc[4][4];
#pragma unroll
    for (int i = 0; i < 4; ++i)
#pragma unroll
        for (int j = 0; j < 4; ++j) acc[i][j] = 0.0f;

#pragma unroll
    for (int kt = 0; kt < 4; ++kt) {
        const int cur = kt & 1;
        if (kt < 3) LDG_TILE(kbase + (kt + 1) * 32);
#pragma unroll
        for (int kk = 0; kk < 32; ++kk) {
            float4 av = *(const float4*)&S.xs[cur][kk][ty * 4];
            float4 bv = *(const float4*)&S.ws[cur][kk][tx * 4];
            float a4[4] = {av.x, av.y, av.z, av.w};
            float b4[4] = {bv.x, bv.y, bv.z, bv.w};
#pragma unroll
            for (int i = 0; i < 4; ++i)
#pragma unroll
                for (int j = 0; j < 4; ++j)
                    acc[i][j] = fmaf(a4[i], b4[j], acc[i][j]);
        }
        if (kt < 3) {
            STS_TILE(cur ^ 1);
            __syncthreads();
        }
    }

#pragma unroll
    for (int i = 0; i < 4; ++i) {
        int m = ty * 4 + i;
        float4 v = make_float4(acc[i][0], acc[i][1], acc[i][2], acc[i][3]);
        *(float4*)&g_part[z][g][b0 + m][n0 + tx * 4] = v;
    }
#undef LDG_TILE
#undef STS_TILE
}

// ---------------- update half-batch device body ------------------------------
// 256 threads, 8 rows per block (one warp per C row), k/q cached in smem.
__device__ __forceinline__ void update_half(
    const float* __restrict__ C, float* __restrict__ outC, float* __restrict__ outH,
    int b0, int idx, char* smem_raw)
{
    UpdSmem& U = *(UpdSmem*)smem_raw;

    const int b  = b0 + (idx >> 7);         // 128 blocks per batch
    const int r0 = (idx & 127) << 3;        // 8 rows per block

    for (int i = threadIdx.x; i < HID; i += 256) {
        U.sk[i] = g_k[b][i];
        U.sq[i] = g_q[b][i];
    }
    __syncthreads();

    const int w    = threadIdx.x >> 5;
    const int lane = threadIdx.x & 31;
    const int r    = r0 + w;

    const float f = g_f[b][r];
    const float a = g_a[b][r];

    const size_t base = ((size_t)b * HID + r) * HID;
    const float4* __restrict__ Crow = (const float4*)(C + base);
    float4* __restrict__ Orow       = (float4*)(outC + base);
    const float4* __restrict__ k4p  = (const float4*)U.sk;
    const float4* __restrict__ q4p  = (const float4*)U.sq;

    float acc = 0.0f;
#pragma unroll
    for (int t = 0; t < 8; ++t) {
        const int j  = lane + t * 32;       // float4 index, coalesced
        float4 c  = Crow[j];
        float4 k4 = k4p[j];
        float4 q4 = q4p[j];
        float4 ct;
        ct.x = fmaf(f, c.x, a * k4.x);
        ct.y = fmaf(f, c.y, a * k4.y);
        ct.z = fmaf(f, c.z, a * k4.z);
        ct.w = fmaf(f, c.w, a * k4.w);
        Orow[j] = ct;
        acc = fmaf(ct.x, q4.x, acc);
        acc = fmaf(ct.y, q4.y, acc);
        acc = fmaf(ct.z, q4.z, acc);
        acc = fmaf(ct.w, q4.w, acc);
    }
#pragma unroll
    for (int off = 16; off > 0; off >>= 1)
        acc += __shfl_xor_sync(0xFFFFFFFFu, acc, off);

    if (lane == 0) {
        const float div = fmaxf(fabsf(g_nq[b]), 1.0f);
        outH[(size_t)b * HID + r] = g_o[b][r] * acc / div;
    }
}

// ---------------- kernels ----------------------------------------------------
__global__ void __launch_bounds__(256) gemm_half_kernel(const float* __restrict__ x,
                                                        WPtrs wp, int b0)
{
    __shared__ __align__(16) char smem_raw[sizeof(GemmSmem)];
    gemm_half(x, wp, b0, blockIdx.x, blockIdx.y, blockIdx.z, smem_raw);
}

// fused: first 384 blocks run gemm for batch half 1; remaining 4096 blocks
// stream the C update for batch half 0. Independent work, complementary pipes.
__global__ void __launch_bounds__(256) fused_kernel(
    const float* __restrict__ x, WPtrs wp,
    const float* __restrict__ C, float* __restrict__ outC, float* __restrict__ outH)
{
    __shared__ __align__(16) char smem_raw[sizeof(GemmSmem)];
    const int bidx = blockIdx.x;
    if (bidx < 384) {
        const int ntile = bidx & 7;
        const int g     = (bidx >> 3) % 6;
        const int z     = bidx / 48;
        gemm_half(x, wp, HB, ntile, g, z, smem_raw);
    } else {
        update_half(C, outC, outH, 0, bidx - 384, smem_raw);
    }
}

__global__ void __launch_bounds__(256) update_half_kernel(
    const float* __restrict__ C, float* __restrict__ outC, float* __restrict__ outH,
    int b0)
{
    __shared__ __align__(16) char smem_raw[sizeof(UpdSmem)];
    update_half(C, outC, outH, b0, blockIdx.x, smem_raw);
}

// ---------------- kernel 2: gate pointwise + per-batch reduction (half) ------
__global__ void __launch_bounds__(256) pointwise_half_kernel(
    const float* __restrict__ nprev, const float* __restrict__ mprev_in,
    WPtrs wp, float* __restrict__ out_n, float* __restrict__ out_m, int b0)
{
    const int b   = b0 + blockIdx.x;
    const int tid = threadIdx.x;
    float local_nq = 0.0f;

#pragma unroll
    for (int t = 0; t < 4; ++t) {
        const int h = tid + t * 256;
        float s[6];
#pragma unroll
        for (int g = 0; g < 6; ++g) {
            float v = wp.b[g][h];
#pragma unroll
            for (int zz = 0; zz < SPLITK; ++zz) v += g_part[zz][g][b][h];
            s[g] = v;
        }
        const float it   = s[0];
        const float ftil = s[1];
        const float otil = s[2];
        const float qv   = s[3];
        const float kv   = s[4] * (1.0f / 32.0f);   // / sqrt(1024)
        const float vv   = s[5];

        const float ft   = 1.0f / (1.0f + expf(-ftil));
        const float lgf  = (ftil >= 0.0f) ? -log1pf(expf(-ftil))
                                          : (ftil - log1pf(expf(ftil)));
        const float mp = mprev_in[(size_t)b * HID + h];
        const float mt = fmaxf(lgf + mp, it);
        const float ip = expf(it - mt);
        const float nt = ft * nprev[(size_t)b * HID + h] + ip * kv;

        out_n[(size_t)b * HID + h] = nt;
        out_m[(size_t)b * HID + h] = mt;
        g_f[b][h] = ft;
        g_a[b][h] = ip * vv;
        g_o[b][h] = 1.0f / (1.0f + expf(-otil));
        g_k[b][h] = kv;
        g_q[b][h] = qv;
        local_nq += nt * qv;
    }

    __shared__ float red[8];
#pragma unroll
    for (int off = 16; off > 0; off >>= 1)
        local_nq += __shfl_xor_sync(0xFFFFFFFFu, local_nq, off);
    if ((tid & 31) == 0) red[tid >> 5] = local_nq;
    __syncthreads();
    if (tid < 8) {
        float v = red[tid];
#pragma unroll
        for (int off = 4; off > 0; off >>= 1)
            v += __shfl_xor_sync(0xFFu, v, off);
        if (tid == 0) g_nq[b] = v;
    }
}

// ---------------- launch ------------------------------------------------------
extern "C" void kernel_launch(void* const* d_in, const int* in_sizes, int n_in,
                              void* d_out, int out_size)
{
    const float* x     = (const float*)d_in[0];
    const float* Cin   = (const float*)d_in[1];
    const float* nprev = (const float*)d_in[2];
    const float* mprev = (const float*)d_in[3];

    WPtrs wp;
    for (int g = 0; g < 6; ++g) {
        wp.W[g] = (const float*)d_in[4 + 2 * g];
        wp.b[g] = (const float*)d_in[5 + 2 * g];
    }

    float* out  = (float*)d_out;
    float* outH = out;                                       // (64,1024)
    float* outC = out + (size_t)BATCH * HID;                 // (64,1024,1024)
    float* outN = outC + (size_t)BATCH * HID * HID;          // (64,1024)
    float* outM = outN + (size_t)BATCH * HID;                // (64,1024)

    // half 0 gates
    gemm_half_kernel<<<dim3(8, 6, SPLITK), 256>>>(x, wp, 0);
    pointwise_half_kernel<<<HB, 256>>>(nprev, mprev, wp, outN, outM, 0);
    // update half 0 overlapped with gemm half 1 (independent block roles)
    fused_kernel<<<384 + HB * 128, 256>>>(x, wp, Cin, outC, outH);
    // half 1 gates + update
    pointwise_half_kernel<<<HB, 256>>>(nprev, mprev, wp, outN, outM, HB);
    update_half_kernel<<<HB * 128, 256>>>(Cin, outC, outH, HB);
}